// round 7
// baseline (speedup 1.0000x reference)
#include <cuda_runtime.h>

// out[bh][q*96+v] = K[bh,3,q] * u[v];  u = scale * (q3 @ V) @ W3
// 96 blocks x 768 threads; each block processes TWO bh pairs in parallel
// halves (threads 0-383 -> bh0, 384-767 -> bh1). Single wave on 148 SMs,
// no SM runs two blocks. Named barriers keep the halves decoupled.

#define SD    96
#define C4    24            // float4 columns per row
#define KG    16            // k groups per half
#define KSPAN 6             // 96 / KG
#define HT    (C4 * KG)     // 384 threads per half
#define NT    (2 * HT)      // 768

__global__ __launch_bounds__(NT, 1) void mma73_kernel(
    const float* __restrict__ Q,
    const float* __restrict__ K,
    const float* __restrict__ V,
    const float* __restrict__ DW,
    const int*   __restrict__ uidx_p,
    float* __restrict__ out)
{
    const int tid = threadIdx.x;
    const int h   = tid / HT;          // half 0/1
    const int hl  = tid - h * HT;      // 0..383 within half
    const int c4  = hl % C4;           // 0..23
    const int grp = hl / C4;           // 0..15
    const int bh  = blockIdx.x * 2 + h;

    __shared__ __align__(16) float4 part4[2][KG][C4];
    __shared__ float t_s[2][SD];

    const int uidx = *uidx_p;

    const float4* __restrict__ Vb4 = (const float4*)(V + (size_t)bh * SD * SD);
    const float4* __restrict__ W4  = (const float4*)(DW + (size_t)uidx * SD * SD);
    const size_t qk_base = ((size_t)bh * SD + 3) * SD;

    // ---- front-batched independent loads ----
    float4 v_r[KSPAN], w_r[KSPAN];
    float  q_r[KSPAN], k_r[KSPAN];
    #pragma unroll
    for (int j = 0; j < KSPAN; ++j)
        v_r[j] = Vb4[(grp * KSPAN + j) * C4 + c4];
    #pragma unroll
    for (int j = 0; j < KSPAN; ++j)
        w_r[j] = W4[(grp * KSPAN + j) * C4 + c4];
    #pragma unroll
    for (int j = 0; j < KSPAN; ++j)
        q_r[j] = __ldg(Q + qk_base + grp * KSPAN + j);   // broadcast within warp
    #pragma unroll
    for (int j = 0; j < KSPAN; ++j)
        k_r[j] = __ldg(K + qk_base + j * KG + grp);      // rows for phase 3

    // ---- phase 1 partials: sync-free start ----
    {
        float4 a = make_float4(0.f, 0.f, 0.f, 0.f);
        #pragma unroll
        for (int j = 0; j < KSPAN; ++j) {
            a.x += q_r[j] * v_r[j].x;  a.y += q_r[j] * v_r[j].y;
            a.z += q_r[j] * v_r[j].z;  a.w += q_r[j] * v_r[j].w;
        }
        part4[h][grp][c4] = a;
    }
    asm volatile("bar.sync %0, %1;" :: "r"(h + 1), "r"(HT) : "memory");

    // ---- t reduce: 96 threads per half ----
    if (hl < SD) {
        const float* p = (const float*)part4[h];   // [KG][SD]
        float s = 0.f;
        #pragma unroll
        for (int g = 0; g < KG; ++g) s += p[g * SD + hl];
        t_s[h][hl] = s;
    }
    asm volatile("bar.sync %0, %1;" :: "r"(h + 1), "r"(HT) : "memory");

    // ---- phase 2 partials: u = scale * (t @ W3) ----
    {
        float4 a = make_float4(0.f, 0.f, 0.f, 0.f);
        #pragma unroll
        for (int j = 0; j < KSPAN; ++j) {
            const float ti = t_s[h][grp * KSPAN + j];
            a.x += ti * w_r[j].x;  a.y += ti * w_r[j].y;
            a.z += ti * w_r[j].z;  a.w += ti * w_r[j].w;
        }
        part4[h][grp][c4] = a;
    }
    asm volatile("bar.sync %0, %1;" :: "r"(h + 1), "r"(HT) : "memory");

    // ---- redundant u reduce per thread (kills last barrier) ----
    float4 u4 = make_float4(0.f, 0.f, 0.f, 0.f);
    #pragma unroll
    for (int g = 0; g < KG; ++g) {
        const float4 pg = part4[h][g][c4];
        u4.x += pg.x;  u4.y += pg.y;  u4.z += pg.z;  u4.w += pg.w;
    }
    const float scale = 0.10206207261596575f;   // 1/sqrt(96)
    u4.x *= scale;  u4.y *= scale;  u4.z *= scale;  u4.w *= scale;

    // ---- phase 3: outer product stores, sync-free ----
    float4* __restrict__ O4 = (float4*)(out + (size_t)bh * SD * SD);
    #pragma unroll
    for (int r = 0; r < KSPAN; ++r) {
        const float kq = k_r[r];
        float4 o;
        o.x = kq * u4.x;  o.y = kq * u4.y;
        o.z = kq * u4.z;  o.w = kq * u4.w;
        O4[(r * KG + grp) * C4 + c4] = o;
    }
}

extern "C" void kernel_launch(void* const* d_in, const int* in_sizes, int n_in,
                              void* d_out, int out_size)
{
    const float* Q  = (const float*)d_in[0];
    const float* K  = (const float*)d_in[1];
    const float* V  = (const float*)d_in[2];
    const float* DW = (const float*)d_in[3];
    const int* uidx = (const int*)d_in[4];
    float* out      = (float*)d_out;

    mma73_kernel<<<96, NT>>>(Q, K, V, DW, uidx, out);
}